// round 9
// baseline (speedup 1.0000x reference)
#include <cuda_runtime.h>
#include <cstdint>

// DiscreteAutoregressiveFlow: exact one-hot algebra over Z_257.
// next = (x_t * m[p] + c[p]) mod 257, per-state (m,c) from argmax of W[p]+b.
// Round 9: ONE launch. Grid order = [tables][per batch: extract, zero, BC].
// BC (segmap + last-block stitch/replay/scatter) blocks spin on per-batch
// ready counters; producers precede consumers in bid order -> deadlock-free;
// BC compute overlaps the DRAM streaming of later batches.

#define V       257
#define B       64
#define L       1024
#define SEG     32
#define SEGLEN  32
#define UNITS   4                 // segments per BC block -> 8 BC blocks/batch
#define REP     8                 // table replication factor
#define NST     258               // states 0..256 plus 257 = ZERO
#define TBLK    33                // table blocks (264 warps >= 258)
#define U4PB    ((L * V) / 4)     // 65792 uint4 per batch
#define XBPB    32                // extract blocks per batch
#define XU4     (U4PB / XBPB)     // 2056
#define ZBPB    64                // zero blocks per batch
#define ZU4     (U4PB / ZBPB)     // 1028
#define CBPB    8                 // BC blocks per batch
#define GRPB    (XBPB + ZBPB + CBPB)   // 104
#define DEADE   (66048u << 9)     // dead entry: m=0, c=66048 -> slot 0

// Slot convention: slot 0 = ZERO/dead; slot s in [1,513] = state (s-1) mod 257.
// Step: z = x*m + c (alive z <= 65792); z mod 257 == (z&255)-(z>>8) (mod 257);
// w = lo - hi + 258 in [1,513] alive, 0 for dead trap (hi=258). Branch-free.

__device__ unsigned g_tab[NST];                          // m | c<<9 (or DEADE)
__device__ __align__(16) int   g_xidx[B * L];
__device__ __align__(16) short g_segmap[B * SEG * NST];
__device__ int g_tabdone;                                // all zero-init,
__device__ int g_rdy[B];                                 // self-resetting
__device__ int g_zrdy[B];
__device__ int g_done[B];
__device__ int g_fin;

__device__ __forceinline__ int slot2state(int s) {       // [0,513] -> 0..257
    return (s == 0) ? V : ((s <= V) ? s - 1 : s - (V + 1));
}

__device__ __forceinline__ void mark(const uint4& v, int i4) {
    if (v.x | v.y | v.z | v.w) {
        unsigned a[4] = { v.x, v.y, v.z, v.w };
        int eb = i4 * 4;
        #pragma unroll
        for (int j = 0; j < 4; j++) {
            if (a[j] != 0u) {
                int idx = eb + j;
                int row = idx / V;
                g_xidx[row] = idx - row * V;
            }
        }
    }
}

__global__ void __launch_bounds__(256) k_all(const float* __restrict__ W,
                                             const float* __restrict__ bb,
                                             const int*   __restrict__ inv_table,
                                             const uint4* __restrict__ x,
                                             uint4*       __restrict__ out4) {
    __shared__ unsigned tabR[514 * REP];                 // 16448 B
    __shared__ __align__(16) int   sxs[UNITS * SEGLEN];
    __shared__ __align__(16) int   sx[L];
    __shared__ __align__(16) short smap[SEG * NST];
    __shared__ short entry[SEG];
    __shared__ int   isLast;

    int bid = blockIdx.x;
    int tid = threadIdx.x;

    // ---------------- role: per-state tables ----------------
    if (bid < TBLK) {
        int p    = bid * 8 + (tid >> 5);
        int lane = tid & 31;
        if (p < NST) {                                    // warp-uniform predicate
            const float* wrow = (p < V) ? (W + (size_t)p * (2 * V)) : nullptr;
            int bestj[2];
            #pragma unroll
            for (int h = 0; h < 2; h++) {
                float bv = -3.402823466e38f;
                int   bj = 0;
                for (int j = lane; j < V; j += 32) {
                    int   col = h * V + j;
                    float v   = bb[col] + (wrow ? wrow[col] : 0.0f);
                    if (v > bv) { bv = v; bj = j; }       // first-max == jnp.argmax
                }
                #pragma unroll
                for (int off = 16; off; off >>= 1) {
                    float ov = __shfl_down_sync(0xffffffffu, bv, off);
                    int   oj = __shfl_down_sync(0xffffffffu, bj, off);
                    if (ov > bv || (ov == bv && oj < bj)) { bv = ov; bj = oj; }
                }
                bestj[h] = bj;
            }
            if (lane == 0) {
                int l = bestj[0], s = bestj[1];
                int m = inv_table[s];                     // 0 iff s==0
                unsigned e = DEADE;
                if (m != 0) {
                    int c = (V - (l * m) % V) % V;
                    e = (unsigned)m | ((unsigned)c << 9);
                }
                g_tab[p] = e;
            }
        }
        __threadfence();
        __syncthreads();
        if (tid == 0) atomicAdd(&g_tabdone, 1);
        return;
    }

    int g = bid - TBLK;
    int b = g / GRPB;
    int r = g - b * GRPB;

    // ---------------- role: extract (read stream) ----------------
    if (r < XBPB) {
        int base = b * U4PB + r * XU4;                    // 2056 uint4
        uint4 v[8];
        #pragma unroll
        for (int k = 0; k < 8; k++) v[k] = x[base + tid + k * 256];
        bool hasx = tid < (XU4 - 2048);                   // 8 ragged
        uint4 vx;
        if (hasx) vx = x[base + 2048 + tid];
        #pragma unroll
        for (int k = 0; k < 8; k++) mark(v[k], base + tid + k * 256);
        if (hasx) mark(vx, base + 2048 + tid);
        __threadfence();
        __syncthreads();
        if (tid == 0) atomicAdd(&g_rdy[b], 1);
        return;
    }

    // ---------------- role: zero-fill (write stream) ----------------
    if (r < XBPB + ZBPB) {
        int base = b * U4PB + (r - XBPB) * ZU4;           // 1028 uint4
        uint4 z = make_uint4(0u, 0u, 0u, 0u);
        #pragma unroll
        for (int k = 0; k < 4; k++) out4[base + tid + k * 256] = z;
        if (tid < (ZU4 - 1024)) out4[base + 1024 + tid] = z;   // 4 ragged
        __threadfence();
        __syncthreads();
        if (tid == 0) atomicAdd(&g_zrdy[b], 1);
        return;
    }

    // ---------------- role: BC (segmap + last-block stitch) ----------------
    int s0 = (r - XBPB - ZBPB) * UNITS;

    if (tid == 0) {
        while (*(volatile int*)&g_tabdone < TBLK) __nanosleep(64);
        while (*(volatile int*)&g_rdy[b]   < XBPB) __nanosleep(64);
    }
    __syncthreads();
    __threadfence();                                      // acquire producers

    for (int i = tid; i < 514 * REP; i += 256)
        tabR[i] = g_tab[slot2state(i >> 3)];              // REP = 8
    if (tid < UNITS * SEGLEN) {
        int u = tid >> 5, t = tid & 31;                   // coalesced LDG
        sxs[t * 4 + u] = g_xidx[b * L + (s0 + u) * SEGLEN + t];
    }
    __syncthreads();

    // segment maps: branch-free dependent chains (4/thread + extra on t<8)
    int rep = tid & (REP - 1);
    int xst = 256 + (tid & 1);
    int xun = (tid >> 1) & 3;
    bool extra = (tid < 8);

    int slot[5];
    #pragma unroll
    for (int j = 0; j < 4; j++) slot[j] = tid + 1;        // state tid -> slot tid+1
    slot[4] = (xst == V) ? 0 : xst + 1;

    #pragma unroll 4
    for (int t = 0; t < SEGLEN; t++) {
        uint4 xv = *(const uint4*)&sxs[t * 4];            // broadcast LDS.128
        unsigned xs[4] = { xv.x, xv.y, xv.z, xv.w };
        #pragma unroll
        for (int j = 0; j < 4; j++) {
            unsigned e = tabR[slot[j] * REP + rep];
            unsigned z = xs[j] * (e & 511u) + (e >> 9);
            slot[j] = (int)(z & 255u) - (int)(z >> 8) + 258;
        }
        if (extra) {
            unsigned e = tabR[slot[4] * REP + rep];
            unsigned z = (unsigned)sxs[t * 4 + xun] * (e & 511u) + (e >> 9);
            slot[4] = (int)(z & 255u) - (int)(z >> 8) + 258;
        }
    }

    short* seg0 = g_segmap + (size_t)(b * SEG + s0) * NST;
    #pragma unroll
    for (int j = 0; j < 4; j++)
        seg0[j * NST + tid] = (short)slot2state(slot[j]);
    if (extra)
        seg0[xun * NST + xst] = (short)slot2state(slot[4]);

    __threadfence();
    __syncthreads();
    if (tid == 0) isLast = (atomicAdd(&g_done[b], 1) == CBPB - 1);
    __syncthreads();
    if (!isLast) return;
    __threadfence();                                      // acquire peers' segmaps

    // last BC block of this batch: stitch + replay + scatter
    ((uint4*)sx)[tid] = ((const uint4*)(g_xidx + b * L))[tid];
    {
        const uint4* src = (const uint4*)(g_segmap + (size_t)b * SEG * NST);
        uint4* dst = (uint4*)smap;
        #pragma unroll
        for (int k = 0; k < 4; k++) dst[tid + 256 * k] = src[tid + 256 * k];
        const int rem = (SEG * NST * 2) / 16 - 1024;      // 8
        if (tid < rem) dst[1024 + tid] = src[1024 + tid];
    }
    __syncthreads();

    if (tid == 0) {
        int st = V;   // ZERO
        #pragma unroll
        for (int s = 0; s < SEG; s++) { entry[s] = (short)st; st = smap[s * NST + st]; }
        while (*(volatile int*)&g_zrdy[b] < ZBPB) __nanosleep(64);  // zeros done
    }
    __syncthreads();
    __threadfence();

    if (tid < SEG) {
        int s   = tid;
        int ent = entry[s];
        int sl  = (ent == V) ? 0 : ent + 1;
        float* orow = (float*)out4 + (size_t)(b * L + s * SEGLEN) * V;
        #pragma unroll 8
        for (int t = 0; t < SEGLEN; t++) {
            unsigned e = tabR[sl * REP + (tid & (REP - 1))];
            unsigned z = (unsigned)sx[s * SEGLEN + t] * (e & 511u) + (e >> 9);
            sl = (int)(z & 255u) - (int)(z >> 8) + 258;
            if (sl != 0) {
                int oi = (sl <= V) ? sl - 1 : sl - (V + 1);
                orow[(size_t)t * V + oi] = 1.0f;
            }
        }
    }
    __syncthreads();

    if (tid == 0) {                                       // self-reset for replay
        g_rdy[b]  = 0;
        g_zrdy[b] = 0;
        g_done[b] = 0;
        int old = atomicAdd(&g_fin, 1);
        if (old == B - 1) { g_tabdone = 0; g_fin = 0; }
    }
}

// ---------------------------------------------------------------------------
extern "C" void kernel_launch(void* const* d_in, const int* in_sizes, int n_in,
                              void* d_out, int out_size) {
    const float* x   = (const float*)d_in[0];   // [B, L, V] f32
    const float* W   = (const float*)d_in[1];   // [V, 2V]   f32
    const float* bb  = (const float*)d_in[2];   // [2V]      f32
    const int*   inv = (const int*)  d_in[3];   // [V]       i32

    k_all<<<TBLK + B * GRPB, 256>>>(W, bb, inv, (const uint4*)x, (uint4*)d_out);
}

// round 10
// speedup vs baseline: 1.1661x; 1.1661x over previous
#include <cuda_runtime.h>
#include <cstdint>

// DiscreteAutoregressiveFlow: exact one-hot algebra over Z_257.
// next = (x_t * m[p] + c[p]) mod 257, per-state (m,c) from argmax of W[p]+b.
// Round 10: back to TWO launches (round-9 fusion poisoned streaming blocks
// with BC smem). k_A unchanged. k_BC: SEG=64 x SEGLEN=16, UNITS=8 -> 8
// interleaved chains per thread (2x ILP), same 512-block grid.

#define V       257
#define B       64
#define L       1024
#define SEG     64
#define SEGLEN  16
#define UNITS   8            // segments per BC block -> 8 blocks per batch
#define BPB     (SEG / UNITS)             // 8
#define SEGBLK  (BPB * B)                 // 512 blocks
#define REP     8                         // table replication factor
#define NST     258                       // states 0..256 plus 257 = ZERO
#define TOTAL4  ((B * L * V) / 4)         // 4,214,784 uint4
#define TBLK    33                        // table blocks (264 warps >= 258)
#define MIXB    (TOTAL4 / 2048)           // 2058 blocks per role (exact)
#define DEADE   (66048u << 9)             // dead: m=0, c=66048 -> slot 0

// Slot convention: slot 0 = ZERO/dead; slot s in [1,513] = state (s-1) mod 257.
// Step: z = x*m + c (alive z <= 65792); z mod 257 == (z&255)-(z>>8) (mod 257);
// w = lo - hi + 258 in [1,513] alive, 0 for the dead trap (hi=258). Branch-free.

__device__ unsigned g_tab[NST];                          // m | c<<9 (or DEADE)
__device__ __align__(16) int   g_xidx[B * L];
__device__ __align__(16) short g_segmap[B * SEG * NST];  // 2.1 MB
__device__ int g_done[B];                                // zero-init; self-reset

__device__ __forceinline__ int slot2state(int s) {       // [0,513] -> 0..257
    return (s == 0) ? V : ((s <= V) ? s - 1 : s - (V + 1));
}

// ---------------------------------------------------------------------------
// K_A: three block roles; read stream (extract) and write stream (zero-fill)
// share the HBM pipe; tables computed by the first 33 blocks. (Unchanged —
// measured ~18.8us, near the 134MB traffic floor.)
// ---------------------------------------------------------------------------
__global__ void __launch_bounds__(256) k_A(const float* __restrict__ W,
                                           const float* __restrict__ bb,
                                           const int*   __restrict__ inv_table,
                                           const uint4* __restrict__ x,
                                           uint4*       __restrict__ out) {
    int bid = blockIdx.x;
    int tid = threadIdx.x;

    if (bid < TBLK) {
        int p    = bid * 8 + (tid >> 5);
        int lane = tid & 31;
        if (p >= NST) return;
        const float* wrow = (p < V) ? (W + (size_t)p * (2 * V)) : nullptr;
        int bestj[2];
        #pragma unroll
        for (int h = 0; h < 2; h++) {
            float bv = -3.402823466e38f;
            int   bj = 0;
            for (int j = lane; j < V; j += 32) {
                int   col = h * V + j;
                float v   = bb[col] + (wrow ? wrow[col] : 0.0f);
                if (v > bv) { bv = v; bj = j; }     // first-max == jnp.argmax
            }
            #pragma unroll
            for (int off = 16; off; off >>= 1) {
                float ov = __shfl_down_sync(0xffffffffu, bv, off);
                int   oj = __shfl_down_sync(0xffffffffu, bj, off);
                if (ov > bv || (ov == bv && oj < bj)) { bv = ov; bj = oj; }
            }
            bestj[h] = bj;
        }
        if (lane == 0) {
            int l = bestj[0], s = bestj[1];
            int m = inv_table[s];                 // 0 iff s==0
            unsigned e = DEADE;
            if (m != 0) {
                int c = (V - (l * m) % V) % V;    // (-l*m) mod V
                e = (unsigned)m | ((unsigned)c << 9);
            }
            g_tab[p] = e;
        }
        return;
    }

    int mm   = bid - TBLK;
    int unit = mm >> 1;
    int base = unit * 2048 + tid;

    if (mm & 1) {
        uint4 z = make_uint4(0u, 0u, 0u, 0u);
        #pragma unroll
        for (int k = 0; k < 8; k++) out[base + k * 256] = z;
        return;
    }

    // extract: 8 coalesced uint4 loads front-batched (MLP_p1 = 8)
    uint4 v[8];
    #pragma unroll
    for (int k = 0; k < 8; k++) v[k] = x[base + k * 256];
    #pragma unroll
    for (int k = 0; k < 8; k++) {
        if (v[k].x | v[k].y | v[k].z | v[k].w) {
            unsigned a[4] = { v[k].x, v[k].y, v[k].z, v[k].w };
            int eb = (base + k * 256) * 4;
            #pragma unroll
            for (int j = 0; j < 4; j++) {
                if (a[j] != 0u) {
                    int idx = eb + j;
                    int row = idx / V;
                    g_xidx[row] = idx - row * V;
                }
            }
        }
    }
}

// ---------------------------------------------------------------------------
// K_BC: segmap (8 chains/thread, 16-step segments) + per-batch last-block
// stitch/replay/scatter. Dynamic smem carve-up:
//   [0, 16448)        unsigned tabR[514*REP]
//   [16448, 20544)    int      sx[L]
//   [20544, 53568)    short    smap[SEG*NST]
// ---------------------------------------------------------------------------
#define SM_TABR  0
#define SM_SX    16448
#define SM_SMAP  20544
#define SM_TOTAL 53568

extern __shared__ char dynsm[];

__global__ void __launch_bounds__(256) k_BC(float* __restrict__ out) {
    unsigned* tabR = (unsigned*)(dynsm + SM_TABR);
    int*      sx   = (int*)     (dynsm + SM_SX);
    short*    smap = (short*)   (dynsm + SM_SMAP);

    __shared__ __align__(16) int sxs[UNITS * SEGLEN];   // [t*8 + u]
    __shared__ short entry[SEG];
    __shared__ int   isLast;

    int bid = blockIdx.x;
    int tid = threadIdx.x;
    int b   = bid / BPB;
    int s0  = (bid % BPB) * UNITS;

    for (int i = tid; i < 514 * REP; i += 256)
        tabR[i] = g_tab[slot2state(i >> 3)];             // REP = 8
    if (tid < UNITS * SEGLEN) {
        int u = tid >> 4, t = tid & 15;                  // coalesced LDG per unit
        sxs[t * 8 + u] = g_xidx[b * L + (s0 + u) * SEGLEN + t];
    }
    __syncthreads();

    // ---- segment maps: 8 branch-free chains per thread + extra on t<16 ----
    int rep = tid & (REP - 1);
    int xst = 256 + (tid & 1);          // extra-chain state (threads 0..15)
    int xun = (tid >> 1) & 7;           // extra-chain unit
    bool extra = (tid < 16);

    int slot[9];
    #pragma unroll
    for (int j = 0; j < 8; j++) slot[j] = tid + 1;       // state tid -> slot tid+1
    slot[8] = (xst == V) ? 0 : xst + 1;

    #pragma unroll
    for (int t = 0; t < SEGLEN; t++) {
        uint4 xv0 = *(const uint4*)&sxs[t * 8];
        uint4 xv1 = *(const uint4*)&sxs[t * 8 + 4];
        unsigned xs[8] = { xv0.x, xv0.y, xv0.z, xv0.w,
                           xv1.x, xv1.y, xv1.z, xv1.w };
        #pragma unroll
        for (int j = 0; j < 8; j++) {
            unsigned e = tabR[slot[j] * REP + rep];
            unsigned z = xs[j] * (e & 511u) + (e >> 9);
            slot[j] = (int)(z & 255u) - (int)(z >> 8) + 258;
        }
        if (extra) {
            unsigned e = tabR[slot[8] * REP + rep];
            unsigned z = (unsigned)sxs[t * 8 + xun] * (e & 511u) + (e >> 9);
            slot[8] = (int)(z & 255u) - (int)(z >> 8) + 258;
        }
    }

    short* seg0 = g_segmap + (size_t)(b * SEG + s0) * NST;
    #pragma unroll
    for (int j = 0; j < 8; j++)
        seg0[j * NST + tid] = (short)slot2state(slot[j]);
    if (extra)
        seg0[xun * NST + xst] = (short)slot2state(slot[8]);

    // ---- publish + elect last block of this batch ----
    __threadfence();
    __syncthreads();
    if (tid == 0) isLast = (atomicAdd(&g_done[b], 1) == BPB - 1);
    __syncthreads();
    if (!isLast) return;
    __threadfence();                     // acquire peers' segmap writes

    // ---- last block: load batch data, stitch, replay, scatter ----
    ((uint4*)sx)[tid] = ((const uint4*)(g_xidx + b * L))[tid];
    {
        const uint4* src = (const uint4*)(g_segmap + (size_t)b * SEG * NST);
        uint4* dst = (uint4*)smap;
        #pragma unroll
        for (int k = 0; k < 8; k++) dst[tid + 256 * k] = src[tid + 256 * k];
        const int rem = (SEG * NST * 2) / 16 - 2048;     // 16
        if (tid < rem) dst[2048 + tid] = src[2048 + tid];
    }
    __syncthreads();

    if (tid == 0) {
        int st = V;   // ZERO
        #pragma unroll
        for (int s = 0; s < SEG; s++) { entry[s] = (short)st; st = smap[s * NST + st]; }
        g_done[b] = 0;                   // self-reset for next graph replay
    }
    __syncthreads();

    if (tid < SEG) {
        int s   = tid;
        int ent = entry[s];
        int sl  = (ent == V) ? 0 : ent + 1;
        float* orow = out + (size_t)(b * L + s * SEGLEN) * V;
        #pragma unroll
        for (int t = 0; t < SEGLEN; t++) {
            unsigned e = tabR[sl * REP + (tid & (REP - 1))];
            unsigned z = (unsigned)sx[s * SEGLEN + t] * (e & 511u) + (e >> 9);
            sl = (int)(z & 255u) - (int)(z >> 8) + 258;
            if (sl != 0) {
                int oi = (sl <= V) ? sl - 1 : sl - (V + 1);
                orow[(size_t)t * V + oi] = 1.0f;
            }
        }
    }
}

// ---------------------------------------------------------------------------
extern "C" void kernel_launch(void* const* d_in, const int* in_sizes, int n_in,
                              void* d_out, int out_size) {
    const float* x   = (const float*)d_in[0];   // [B, L, V] f32
    const float* W   = (const float*)d_in[1];   // [V, 2V]   f32
    const float* bb  = (const float*)d_in[2];   // [2V]      f32
    const int*   inv = (const int*)  d_in[3];   // [V]       i32

    cudaFuncSetAttribute(k_BC, cudaFuncAttributeMaxDynamicSharedMemorySize,
                         SM_TOTAL);

    k_A<<<TBLK + 2 * MIXB, 256>>>(W, bb, inv, (const uint4*)x, (uint4*)d_out);
    k_BC<<<SEGBLK, 256, SM_TOTAL>>>((float*)d_out);
}